// round 6
// baseline (speedup 1.0000x reference)
#include <cuda_runtime.h>
#include <cuda_fp16.h>
#include <cstdint>

// Problem constants
#define BB 4
#define CC 3
#define HH 384
#define WW 384
#define KK 5
#define K2 25
#define HWSZ (HH * WW)          // 147456
#define NUM_ITER 20
#define INVZ2 44.4444444444444444f   // 1 / 0.15^2

// ---------------- precompute tile ----------------
#define PTX 32
#define PTY 16
#define PLX (PTX + 4)
#define PLY (PTY + 4)

// ---------------- persistent kernel geometry ----------------
// 288 blocks (6 x 12 x 4), 512 threads (32 x 16), each thread owns a 2x2
// pixel quad -> tile = 64 x 32 pixels. 2 blocks/SM x 148 SMs = 296 >= 288,
// so ALL blocks are co-resident and a software grid barrier is safe.
#define TILE_W 64
#define TILE_H 32
#define XS_W (TILE_W + 4)    // 68
#define XS_H (TILE_H + 4)    // 36
#define NQ 512               // quads per block
#define GRID_X (WW / TILE_W) // 6
#define GRID_Y (HH / TILE_H) // 12
#define NBLK (GRID_X * GRID_Y * BB)  // 288

#define SMEM_W_BYTES (K2 * NQ * 8)                 // 102400
#define SMEM_X_BYTES (XS_H * XS_W * 4)             // 9792
#define SMEM_DYN (SMEM_W_BYTES + SMEM_X_BYTES)     // 112192

// Scratch (global):
//  g_wp : 25 half planes per batch (fp16 normalized weights)  -> 29.5 MB
//  g_c  : fp32 plane: mask / sum(dequantized fp16 weights)    ->  2.4 MB
//  g_x  : ping-pong x border-exchange buffers (fp32)
//  g_count : grid-barrier counter (reset by precompute each call)
__device__ __half    g_wp[(size_t)BB * K2 * HWSZ];
__device__ float     g_c [(size_t)BB * HWSZ];
__device__ float     g_x[2][(size_t)BB * HWSZ];
__device__ unsigned  g_count;

// ---------------------------------------------------------------------------
// Kernel 1: normalized bilateral weights -> fp16 planes, fp32 renorm factor
// c = mask / sum(dequantized fp16 weights), x0 = feat * mask, and reset the
// grid-barrier counter (kernel-boundary ordering makes it visible).
// img shifted by +10 BEFORE zero padding (matches reference): OOB taps use
// padded value 0 and their affinity underflows to exactly 0.
// ---------------------------------------------------------------------------
__global__ void __launch_bounds__(512) precompute_kernel(
    const float* __restrict__ img,
    const float* __restrict__ feat,
    const float* __restrict__ mask)
{
    if (blockIdx.x == 0 && blockIdx.y == 0 && blockIdx.z == 0 &&
        threadIdx.x == 0 && threadIdx.y == 0)
        g_count = 0u;

    __shared__ float s[PLY][PLX][CC];

    const int b  = blockIdx.z;
    const int h0 = blockIdx.y * PTY;
    const int w0 = blockIdx.x * PTX;
    const int tx = threadIdx.x, ty = threadIdx.y;
    const int tid = ty * PTX + tx;

    const float* imb = img + (size_t)b * CC * HWSZ;

    for (int i = tid; i < PLY * PLX; i += PTX * PTY) {
        int ly = i / PLX, lx = i - ly * PLX;
        int gh = h0 + ly - 2, gw = w0 + lx - 2;
        bool ok = (gh >= 0) && (gh < HH) && (gw >= 0) && (gw < WW);
        #pragma unroll
        for (int c = 0; c < CC; c++)
            s[ly][lx][c] = ok ? imb[(size_t)c * HWSZ + gh * WW + gw] + 10.0f : 0.0f;
    }
    __syncthreads();

    const float c0 = s[ty + 2][tx + 2][0];
    const float c1 = s[ty + 2][tx + 2][1];
    const float c2 = s[ty + 2][tx + 2][2];

    float aff[K2];
    float sum = 0.0f;
    #pragma unroll
    for (int k = 0; k < K2; k++) {
        const int dy = k / KK, dx = k % KK;
        float d0 = s[ty + dy][tx + dx][0] - c0;
        float d1 = s[ty + dy][tx + dx][1] - c1;
        float d2 = s[ty + dy][tx + dx][2] - c2;
        float d  = d0 * d0 + d1 * d1 + d2 * d2;
        float a  = __expf(-d * INVZ2);
        aff[k] = a;
        sum += a;
    }
    const float inv = 1.0f / (sum + 1e-10f);

    // Quantize to fp16; renorm by the exact fp32 sum of quantized weights.
    __half q[K2];
    float qs = 0.0f;
    #pragma unroll
    for (int k = 0; k < K2; k++) {
        q[k] = __float2half_rn(aff[k] * inv);
        qs += __half2float(q[k]);
    }

    const int gh = h0 + ty, gw = w0 + tx;
    const size_t pix = (size_t)gh * WW + gw;
    const size_t p = (size_t)b * HWSZ + pix;

    __half* wb = g_wp + (size_t)b * K2 * HWSZ + pix;
    #pragma unroll
    for (int k = 0; k < K2; k++)
        wb[(size_t)k * HWSZ] = q[k];

    const float mk = mask[p];
    g_c[p] = mk / qs;                 // mask folded into renorm factor
    g_x[0][p] = feat[p] * mk;
}

// ---------------------------------------------------------------------------
// Kernel 2: persistent — all 20 iterations. Weights live in smem for the
// whole kernel; x interior lives in smem; only a 2-wide border ring is
// exchanged through global ping-pong buffers between grid barriers.
// ---------------------------------------------------------------------------
__global__ void __launch_bounds__(512, 2) persist_kernel(
    float* __restrict__ out)
{
    extern __shared__ char smem_raw[];
    uint2* ws = reinterpret_cast<uint2*>(smem_raw);                   // [25][NQ]
    float* xs = reinterpret_cast<float*>(smem_raw + SMEM_W_BYTES);    // [XS_H][XS_W]

    const int tx = threadIdx.x, ty = threadIdx.y;
    const int tid = ty * 32 + tx;
    const int quad = tid;

    const int b  = blockIdx.z;
    const int h0 = blockIdx.y * TILE_H;
    const int w0 = blockIdx.x * TILE_W;

    const int r0 = 2 * ty;          // local px rows r0, r0+1
    const int c0 = 2 * tx;          // local px cols c0, c0+1
    const size_t p00 = (size_t)(h0 + r0)     * WW + (w0 + c0);
    const size_t p10 = (size_t)(h0 + r0 + 1) * WW + (w0 + c0);

    // ---- one-time: weights -> smem (uint2 = {half2 row0, half2 row1}) ----
    const __half* wp = g_wp + (size_t)b * K2 * HWSZ;
    #pragma unroll
    for (int k = 0; k < K2; k++) {
        unsigned lo = *reinterpret_cast<const unsigned*>(wp + (size_t)k * HWSZ + p00);
        unsigned hi = *reinterpret_cast<const unsigned*>(wp + (size_t)k * HWSZ + p10);
        ws[k * NQ + quad] = make_uint2(lo, hi);
    }

    // renorm factors (mask folded) — register resident
    const float* cb = g_c + (size_t)b * HWSZ;
    const float2 cf0 = *reinterpret_cast<const float2*>(cb + p00);
    const float2 cf1 = *reinterpret_cast<const float2*>(cb + p10);

    // ---- one-time: interior x -> smem ----
    {
        const float* x0g = &g_x[0][(size_t)b * HWSZ];
        float2 i0 = *reinterpret_cast<const float2*>(x0g + p00);
        float2 i1 = *reinterpret_cast<const float2*>(x0g + p10);
        *reinterpret_cast<float2*>(&xs[(r0 + 2) * XS_W + c0 + 2]) = i0;
        *reinterpret_cast<float2*>(&xs[(r0 + 3) * XS_W + c0 + 2]) = i1;
    }

    const bool border0 = (r0 < 2) || (r0 >= TILE_H - 2) || (c0 < 2) || (c0 + 1 >= TILE_W - 2);
    const bool border1 = (r0 + 1 < 2) || (r0 + 1 >= TILE_H - 2) || (c0 < 2) || (c0 + 1 >= TILE_W - 2);

    for (int it = 0; it < NUM_ITER; it++) {
        // ---- halo ring from global (neighbors' previous-iter borders) ----
        const float* src = &g_x[it & 1][(size_t)b * HWSZ];
        for (int i = tid; i < XS_H * XS_W; i += 512) {
            int ly = i / XS_W, lx = i - ly * XS_W;
            if (ly >= 2 && ly < XS_H - 2 && lx >= 2 && lx < XS_W - 2) continue;
            int gh = h0 + ly - 2, gw = w0 + lx - 2;
            bool ok = (gh >= 0) && (gh < HH) && (gw >= 0) && (gw < WW);
            xs[ly * XS_W + lx] = ok ? src[gh * WW + gw] : 0.0f;
        }
        __syncthreads();

        // ---- compute 2x2 quad ----
        float a00 = 0.f, a01 = 0.f, a10 = 0.f, a11 = 0.f;
        uint2 Wp[5];
        #pragma unroll
        for (int j = 0; j < 6; j++) {
            const float* row = &xs[(r0 + j) * XS_W + c0];
            float2 va = *reinterpret_cast<const float2*>(row);
            float2 vb = *reinterpret_cast<const float2*>(row + 2);
            float2 vc = *reinterpret_cast<const float2*>(row + 4);
            float2 vd = *reinterpret_cast<const float2*>(row + 6);
            float v[7] = { va.x, va.y, vb.x, vb.y, vc.x, vc.y, vd.x };

            uint2 Wc[5];
            if (j < 5) {
                #pragma unroll
                for (int dx = 0; dx < 5; dx++)
                    Wc[dx] = ws[(j * 5 + dx) * NQ + quad];
            }
            #pragma unroll
            for (int dx = 0; dx < 5; dx++) {
                if (j < 5) {
                    float2 fA = __half22float2(*reinterpret_cast<__half2*>(&Wc[dx].x));
                    a00 = fmaf(fA.x, v[dx], a00);
                    a01 = fmaf(fA.y, v[dx + 1], a01);
                }
                if (j >= 1) {
                    float2 fB = __half22float2(*reinterpret_cast<__half2*>(&Wp[dx].y));
                    a10 = fmaf(fB.x, v[dx], a10);
                    a11 = fmaf(fB.y, v[dx + 1], a11);
                }
            }
            if (j < 5) {
                #pragma unroll
                for (int dx = 0; dx < 5; dx++) Wp[dx] = Wc[dx];
            }
        }

        const float o00 = a00 * cf0.x, o01 = a01 * cf0.y;
        const float o10 = a10 * cf1.x, o11 = a11 * cf1.y;

        __syncthreads();   // all reads of xs done before overwrite

        *reinterpret_cast<float2*>(&xs[(r0 + 2) * XS_W + c0 + 2]) = make_float2(o00, o01);
        *reinterpret_cast<float2*>(&xs[(r0 + 3) * XS_W + c0 + 2]) = make_float2(o10, o11);

        if (it == NUM_ITER - 1) {
            // final: write full frame to out, no barrier needed
            float* ob = out + (size_t)b * HWSZ;
            *reinterpret_cast<float2*>(ob + p00) = make_float2(o00, o01);
            *reinterpret_cast<float2*>(ob + p10) = make_float2(o10, o11);
        } else {
            // publish my 2-wide border for neighbors' next-iter halo
            float* dst = &g_x[(it + 1) & 1][(size_t)b * HWSZ];
            if (border0) *reinterpret_cast<float2*>(dst + p00) = make_float2(o00, o01);
            if (border1) *reinterpret_cast<float2*>(dst + p10) = make_float2(o10, o11);

            // ---- grid barrier (all 288 blocks co-resident) ----
            __syncthreads();
            if (tid == 0) {
                __threadfence();
                const unsigned target = (unsigned)(it + 1) * NBLK;
                atomicAdd(&g_count, 1u);
                while (*(volatile unsigned*)&g_count < target)
                    __nanosleep(64);
                __threadfence();
            }
            __syncthreads();
        }
    }
}

// ---------------------------------------------------------------------------
extern "C" void kernel_launch(void* const* d_in, const int* in_sizes, int n_in,
                              void* d_out, int out_size)
{
    const float* img  = (const float*)d_in[0];
    const float* feat = (const float*)d_in[1];
    const float* mask = (const float*)d_in[2];
    float* out = (float*)d_out;

    cudaFuncSetAttribute(persist_kernel,
                         cudaFuncAttributeMaxDynamicSharedMemorySize, SMEM_DYN);

    dim3 pblk(PTX, PTY);
    dim3 pgrd(WW / PTX, HH / PTY, BB);    // (12, 24, 4)
    precompute_kernel<<<pgrd, pblk>>>(img, feat, mask);

    dim3 iblk(32, 16);
    dim3 igrd(GRID_X, GRID_Y, BB);        // (6, 12, 4) = 288 blocks
    persist_kernel<<<igrd, iblk, SMEM_DYN>>>(out);
}

// round 7
// speedup vs baseline: 1.3027x; 1.3027x over previous
#include <cuda_runtime.h>
#include <cuda_fp16.h>
#include <cstdint>

// Problem constants
#define BB 4
#define CC 3
#define HH 384
#define WW 384
#define KK 5
#define K2 25
#define HWSZ (HH * WW)          // 147456
#define NUM_ITER 20
#define INVZ2 44.4444444444444444f   // 1 / 0.15^2

// ---------------- precompute tile ----------------
#define PTX 32
#define PTY 16
#define PLX (PTX + 4)
#define PLY (PTY + 4)

// ---------------- persistent kernel geometry ----------------
// 288 blocks (6 x 12 x 4), 512 threads (32 x 16), each thread owns a 2x2
// pixel quad -> tile = 64 x 32 pixels. 2 blocks/SM x 148 SMs = 296 >= 288,
// so ALL blocks are co-resident (required: neighbor flag-sync would
// deadlock on a non-resident block).
#define TILE_W 64
#define TILE_H 32
#define XS_W (TILE_W + 4)    // 68
#define XS_H (TILE_H + 4)    // 36
#define NQ 512               // quads per block
#define GRID_X (WW / TILE_W) // 6
#define GRID_Y (HH / TILE_H) // 12
#define NBLK (GRID_X * GRID_Y * BB)  // 288
#define RING_N 400           // halo ring elements: 2*(2*68) + 2*(2*32)

#define SMEM_W_BYTES (K2 * NQ * 8)                 // 102400
#define SMEM_X_BYTES (XS_H * XS_W * 4)             // 9792
#define SMEM_DYN (SMEM_W_BYTES + SMEM_X_BYTES)     // 112192

// Scratch (global):
__device__ __half    g_wp[(size_t)BB * K2 * HWSZ];   // fp16 normalized weights
__device__ float     g_c [(size_t)BB * HWSZ];        // mask / sum(quantized w)
__device__ float     g_x[2][(size_t)BB * HWSZ];      // ping-pong border exchange
__device__ int       g_flag[NBLK];                   // per-block progress flags

// ---------------------------------------------------------------------------
// Kernel 1: normalized bilateral weights -> fp16 planes, fp32 renorm factor
// c = mask / sum(dequantized fp16 weights), x0 = feat * mask, flag reset.
// img shifted by +10 BEFORE zero padding (matches reference): OOB taps use
// padded value 0 and their affinity underflows to exactly 0.
// ---------------------------------------------------------------------------
__global__ void __launch_bounds__(512) precompute_kernel(
    const float* __restrict__ img,
    const float* __restrict__ feat,
    const float* __restrict__ mask)
{
    // reset progress flags (kernel-boundary ordering makes this visible
    // to persist_kernel)
    {
        int bflat = (blockIdx.z * gridDim.y + blockIdx.y) * gridDim.x + blockIdx.x;
        if (threadIdx.x == 0 && threadIdx.y == 0 && bflat < NBLK)
            g_flag[bflat] = 0;
    }

    __shared__ float s[PLY][PLX][CC];

    const int b  = blockIdx.z;
    const int h0 = blockIdx.y * PTY;
    const int w0 = blockIdx.x * PTX;
    const int tx = threadIdx.x, ty = threadIdx.y;
    const int tid = ty * PTX + tx;

    const float* imb = img + (size_t)b * CC * HWSZ;

    for (int i = tid; i < PLY * PLX; i += PTX * PTY) {
        int ly = i / PLX, lx = i - ly * PLX;
        int gh = h0 + ly - 2, gw = w0 + lx - 2;
        bool ok = (gh >= 0) && (gh < HH) && (gw >= 0) && (gw < WW);
        #pragma unroll
        for (int c = 0; c < CC; c++)
            s[ly][lx][c] = ok ? imb[(size_t)c * HWSZ + gh * WW + gw] + 10.0f : 0.0f;
    }
    __syncthreads();

    const float c0 = s[ty + 2][tx + 2][0];
    const float c1 = s[ty + 2][tx + 2][1];
    const float c2 = s[ty + 2][tx + 2][2];

    float aff[K2];
    float sum = 0.0f;
    #pragma unroll
    for (int k = 0; k < K2; k++) {
        const int dy = k / KK, dx = k % KK;
        float d0 = s[ty + dy][tx + dx][0] - c0;
        float d1 = s[ty + dy][tx + dx][1] - c1;
        float d2 = s[ty + dy][tx + dx][2] - c2;
        float d  = d0 * d0 + d1 * d1 + d2 * d2;
        float a  = __expf(-d * INVZ2);
        aff[k] = a;
        sum += a;
    }
    const float inv = 1.0f / (sum + 1e-10f);

    __half q[K2];
    float qs = 0.0f;
    #pragma unroll
    for (int k = 0; k < K2; k++) {
        q[k] = __float2half_rn(aff[k] * inv);
        qs += __half2float(q[k]);
    }

    const int gh = h0 + ty, gw = w0 + tx;
    const size_t pix = (size_t)gh * WW + gw;
    const size_t p = (size_t)b * HWSZ + pix;

    __half* wb = g_wp + (size_t)b * K2 * HWSZ + pix;
    #pragma unroll
    for (int k = 0; k < K2; k++)
        wb[(size_t)k * HWSZ] = q[k];

    const float mk = mask[p];
    g_c[p] = mk / qs;
    g_x[0][p] = feat[p] * mk;
}

// ---------------------------------------------------------------------------
// Kernel 2: persistent — all 20 iterations, neighbor-local flag sync.
// ---------------------------------------------------------------------------
__global__ void __launch_bounds__(512, 2) persist_kernel(
    float* __restrict__ out)
{
    extern __shared__ char smem_raw[];
    uint2* ws = reinterpret_cast<uint2*>(smem_raw);                   // [25][NQ]
    float* xs = reinterpret_cast<float*>(smem_raw + SMEM_W_BYTES);    // [XS_H][XS_W]

    const int tx = threadIdx.x, ty = threadIdx.y;
    const int tid = ty * 32 + tx;
    const int quad = tid;

    const int b  = blockIdx.z;
    const int bx = blockIdx.x, by = blockIdx.y;
    const int h0 = by * TILE_H;
    const int w0 = bx * TILE_W;
    const int myflat = (b * GRID_Y + by) * GRID_X + bx;

    // neighbor flag indices (same batch, 8-neighborhood)
    int nb[8]; int nnb = 0;
    #pragma unroll
    for (int dy = -1; dy <= 1; dy++)
        #pragma unroll
        for (int dx = -1; dx <= 1; dx++) {
            if (dx == 0 && dy == 0) continue;
            int nx = bx + dx, ny = by + dy;
            if (nx >= 0 && nx < GRID_X && ny >= 0 && ny < GRID_Y)
                nb[nnb++] = (b * GRID_Y + ny) * GRID_X + nx;
        }

    const int r0 = 2 * ty;
    const int c0 = 2 * tx;
    const size_t p00 = (size_t)(h0 + r0)     * WW + (w0 + c0);
    const size_t p10 = (size_t)(h0 + r0 + 1) * WW + (w0 + c0);

    // ---- one-time: weights -> smem ----
    const __half* wp = g_wp + (size_t)b * K2 * HWSZ;
    #pragma unroll
    for (int k = 0; k < K2; k++) {
        unsigned lo = *reinterpret_cast<const unsigned*>(wp + (size_t)k * HWSZ + p00);
        unsigned hi = *reinterpret_cast<const unsigned*>(wp + (size_t)k * HWSZ + p10);
        ws[k * NQ + quad] = make_uint2(lo, hi);
    }

    const float* cb = g_c + (size_t)b * HWSZ;
    const float2 cf0 = *reinterpret_cast<const float2*>(cb + p00);
    const float2 cf1 = *reinterpret_cast<const float2*>(cb + p10);

    // ---- one-time: interior x -> smem ----
    {
        const float* x0g = &g_x[0][(size_t)b * HWSZ];
        float2 i0 = *reinterpret_cast<const float2*>(x0g + p00);
        float2 i1 = *reinterpret_cast<const float2*>(x0g + p10);
        *reinterpret_cast<float2*>(&xs[(r0 + 2) * XS_W + c0 + 2]) = i0;
        *reinterpret_cast<float2*>(&xs[(r0 + 3) * XS_W + c0 + 2]) = i1;
    }

    // direct ring mapping for this thread (tid < RING_N)
    int rly = -1, rlx = 0;
    if (tid < 136)        { rly = tid / 68;            rlx = tid % 68; }
    else if (tid < 272)   { int t = tid - 136; rly = 34 + t / 68; rlx = t % 68; }
    else if (tid < 336)   { int t = tid - 272; rlx = t & 1;       rly = 2 + (t >> 1); }
    else if (tid < 400)   { int t = tid - 336; rlx = 66 + (t & 1); rly = 2 + (t >> 1); }
    int rgh = 0, rgw = 0; bool rok = false;
    if (rly >= 0) {
        rgh = h0 + rly - 2; rgw = w0 + rlx - 2;
        rok = (rgh >= 0) && (rgh < HH) && (rgw >= 0) && (rgw < WW);
    }

    const bool border0 = (r0 < 2) || (r0 >= TILE_H - 2) || (c0 < 2) || (c0 + 1 >= TILE_W - 2);
    const bool border1 = border0;  // same quad columns; rows r0,r0+1 share cond except row edges
    const bool b0row = (r0 < 2) || (r0 >= TILE_H - 2);
    const bool b1row = (r0 + 1 < 2) || (r0 + 1 >= TILE_H - 2);
    const bool bcol  = (c0 < 2) || (c0 + 1 >= TILE_W - 2);
    const bool pub0 = b0row || bcol;
    const bool pub1 = b1row || bcol;
    (void)border0; (void)border1;

    for (int it = 0; it < NUM_ITER; it++) {
        // ---- wait for neighbors to have published x_it borders ----
        if (it > 0) {
            if (tid < nnb) {
                const int* f = &g_flag[nb[tid]];
                while (__ldcg(f) < it) { }
            }
            __threadfence();
            __syncthreads();
        }

        // ---- halo ring from global (L2-coherent reads) ----
        if (rly >= 0) {
            const float* src = &g_x[it & 1][(size_t)b * HWSZ];
            xs[rly * XS_W + rlx] = rok ? __ldcg(src + (size_t)rgh * WW + rgw) : 0.0f;
        }
        __syncthreads();

        // ---- compute 2x2 quad ----
        float a00 = 0.f, a01 = 0.f, a10 = 0.f, a11 = 0.f;
        uint2 Wp[5];
        #pragma unroll
        for (int j = 0; j < 6; j++) {
            const float* row = &xs[(r0 + j) * XS_W + c0];
            float2 va = *reinterpret_cast<const float2*>(row);
            float2 vb = *reinterpret_cast<const float2*>(row + 2);
            float2 vc = *reinterpret_cast<const float2*>(row + 4);
            float2 vd = *reinterpret_cast<const float2*>(row + 6);
            float v[7] = { va.x, va.y, vb.x, vb.y, vc.x, vc.y, vd.x };

            uint2 Wc[5];
            if (j < 5) {
                #pragma unroll
                for (int dx = 0; dx < 5; dx++)
                    Wc[dx] = ws[(j * 5 + dx) * NQ + quad];
            }
            #pragma unroll
            for (int dx = 0; dx < 5; dx++) {
                if (j < 5) {
                    float2 fA = __half22float2(*reinterpret_cast<__half2*>(&Wc[dx].x));
                    a00 = fmaf(fA.x, v[dx], a00);
                    a01 = fmaf(fA.y, v[dx + 1], a01);
                }
                if (j >= 1) {
                    float2 fB = __half22float2(*reinterpret_cast<__half2*>(&Wp[dx].y));
                    a10 = fmaf(fB.x, v[dx], a10);
                    a11 = fmaf(fB.y, v[dx + 1], a11);
                }
            }
            if (j < 5) {
                #pragma unroll
                for (int dx = 0; dx < 5; dx++) Wp[dx] = Wc[dx];
            }
        }

        const float o00 = a00 * cf0.x, o01 = a01 * cf0.y;
        const float o10 = a10 * cf1.x, o11 = a11 * cf1.y;

        __syncthreads();   // all reads of xs done before overwrite

        *reinterpret_cast<float2*>(&xs[(r0 + 2) * XS_W + c0 + 2]) = make_float2(o00, o01);
        *reinterpret_cast<float2*>(&xs[(r0 + 3) * XS_W + c0 + 2]) = make_float2(o10, o11);

        if (it == NUM_ITER - 1) {
            float* ob = out + (size_t)b * HWSZ;
            *reinterpret_cast<float2*>(ob + p00) = make_float2(o00, o01);
            *reinterpret_cast<float2*>(ob + p10) = make_float2(o10, o11);
        } else {
            // publish my 2-wide border for neighbors' next-iter halo
            float* dst = &g_x[(it + 1) & 1][(size_t)b * HWSZ];
            if (pub0) *reinterpret_cast<float2*>(dst + p00) = make_float2(o00, o01);
            if (pub1) *reinterpret_cast<float2*>(dst + p10) = make_float2(o10, o11);

            __threadfence();     // border writes globally visible
            __syncthreads();     // all threads' writes fenced before flag bump
            if (tid == 0)
                atomicExch(&g_flag[myflat], it + 1);
        }
    }
}

// ---------------------------------------------------------------------------
extern "C" void kernel_launch(void* const* d_in, const int* in_sizes, int n_in,
                              void* d_out, int out_size)
{
    const float* img  = (const float*)d_in[0];
    const float* feat = (const float*)d_in[1];
    const float* mask = (const float*)d_in[2];
    float* out = (float*)d_out;

    cudaFuncSetAttribute(persist_kernel,
                         cudaFuncAttributeMaxDynamicSharedMemorySize, SMEM_DYN);

    dim3 pblk(PTX, PTY);
    dim3 pgrd(WW / PTX, HH / PTY, BB);    // (12, 24, 4)
    precompute_kernel<<<pgrd, pblk>>>(img, feat, mask);

    dim3 iblk(32, 16);
    dim3 igrd(GRID_X, GRID_Y, BB);        // (6, 12, 4) = 288 blocks
    persist_kernel<<<igrd, iblk, SMEM_DYN>>>(out);
}